// round 1
// baseline (speedup 1.0000x reference)
#include <cuda_runtime.h>
#include <math.h>

#define NN 50000
#define EE 800000
#define ET (EE + NN)
#define GG 64
#define HID 64
#define CC 8
#define NBLK 49   // ceil(NN/1024)

// ---------------- scratch (static device globals; no allocation) -------------
__device__ __align__(256) float g_lin[NN * HID];   // gemm output (h) per layer
__device__ __align__(256) float g_act[NN * HID];   // post-aggregation activations
__device__ float g_h3[NN * CC];
__device__ float g_as[NN];
__device__ float g_ad[NN];
__device__ int   g_deg[NN];
__device__ int   g_pos[NN];
__device__ int   g_off[NN + 1];
__device__ int   g_esrc[ET];
__device__ int   g_part[NBLK];
__device__ float g_pool[GG * CC];
__device__ int   g_cnt[GG];
__device__ int   g_is64;

// ---------------- index dtype handling (int64 vs int32) ----------------------
__device__ __forceinline__ int ld_idx(const void* p, long long i) {
    return g_is64 ? (int)((const long long*)p)[i] : ((const int*)p)[i];
}

__global__ void k_detect(const void* ei) {
    if (blockIdx.x == 0 && threadIdx.x == 0) {
        const int* p = (const int*)ei;
        int ok = 1;
        // int64 little-endian: high words of node ids (< 2^31) are all zero.
        // int32: these slots are random node ids -> virtually never all zero.
        for (int i = 0; i < 64; i++) ok &= (p[2 * i + 1] == 0);
        g_is64 = ok;
    }
}

// ---------------- CSR build --------------------------------------------------
__global__ void k_zero() {
    int i = blockIdx.x * blockDim.x + threadIdx.x;
    if (i < NN) { g_deg[i] = 0; g_pos[i] = 0; }
    if (i < GG * CC) g_pool[i] = 0.f;
    if (i < GG) g_cnt[i] = 0;
}

__global__ void k_hist(const void* ei) {
    int e = blockIdx.x * blockDim.x + threadIdx.x;
    if (e >= ET) return;
    int d = (e < EE) ? ld_idx(ei, (long long)EE + e) : (e - EE);
    atomicAdd(&g_deg[d], 1);
}

__global__ void k_scan1() {
    __shared__ int s[1024];
    int tid = threadIdx.x;
    int i = blockIdx.x * 1024 + tid;
    int v = (i < NN) ? g_deg[i] : 0;
    s[tid] = v;
    __syncthreads();
    for (int off = 1; off < 1024; off <<= 1) {
        int t = (tid >= off) ? s[tid - off] : 0;
        __syncthreads();
        s[tid] += t;
        __syncthreads();
    }
    if (i < NN) g_off[i + 1] = s[tid];
    if (tid == 1023) g_part[blockIdx.x] = s[1023];
}

__global__ void k_scan2() {
    if (threadIdx.x == 0) {
        int run = 0;
        for (int i = 0; i < NBLK; i++) { int v = g_part[i]; g_part[i] = run; run += v; }
    }
}

__global__ void k_scan3() {
    int i = blockIdx.x * 1024 + threadIdx.x;
    if (i < NN) g_off[i + 1] += g_part[blockIdx.x];
    if (i == 0) g_off[0] = 0;
}

__global__ void k_scatter(const void* ei) {
    int e = blockIdx.x * blockDim.x + threadIdx.x;
    if (e >= ET) return;
    int s, d;
    if (e < EE) { s = ld_idx(ei, e); d = ld_idx(ei, (long long)EE + e); }
    else        { s = d = e - EE; }
    int p = g_off[d] + atomicAdd(&g_pos[d], 1);
    g_esrc[p] = s;
}

// ---------------- GEMM: h = x @ W  (no bias) ---------------------------------
// block = 64 threads; GROUPS = 64/FO groups of FO threads, each group handles
// NPT nodes (register-blocked so W values are reused NPT times per load).
template <int FI, int FO>
__global__ void k_gemm(const float* __restrict__ x, const float* __restrict__ W,
                       float* __restrict__ h) {
    const int NPT = 4;
    const int GROUPS = 64 / FO;
    const int NPB = GROUPS * NPT;
    __shared__ float xs[NPB * FI];
    int tid = threadIdx.x;
    int nodeBase = blockIdx.x * NPB;
    for (int i = tid; i < NPB * FI; i += 64) {
        int n = nodeBase + i / FI;
        xs[i] = (n < NN) ? x[(long long)n * FI + (i % FI)] : 0.f;
    }
    __syncthreads();
    int gq = tid / FO;
    int f = tid % FO;
    float acc[NPT] = {0.f, 0.f, 0.f, 0.f};
    for (int k = 0; k < FI; k++) {
        float w = W[k * FO + f];
#pragma unroll
        for (int i = 0; i < NPT; i++)
            acc[i] += xs[(gq * NPT + i) * FI + k] * w;
    }
#pragma unroll
    for (int i = 0; i < NPT; i++) {
        int n = nodeBase + gq * NPT + i;
        if (n < NN) h[(long long)n * FO + f] = acc[i];
    }
}

// ---------------- per-node attention logits ----------------------------------
template <int F>
__global__ void k_alpha(const float* __restrict__ h, const float* __restrict__ a_s,
                        const float* __restrict__ a_d) {
    int w = (blockIdx.x * blockDim.x + threadIdx.x) >> 5;
    int lane = threadIdx.x & 31;
    if (w >= NN) return;
    float s1 = 0.f, s2 = 0.f;
    if (F == 64) {
        float v0 = h[w * 64 + lane], v1 = h[w * 64 + 32 + lane];
        s1 = v0 * a_s[lane] + v1 * a_s[lane + 32];
        s2 = v0 * a_d[lane] + v1 * a_d[lane + 32];
    } else if (lane < F) {
        float v = h[w * F + lane];
        s1 = v * a_s[lane];
        s2 = v * a_d[lane];
    }
#pragma unroll
    for (int o = 16; o; o >>= 1) {
        s1 += __shfl_xor_sync(0xFFFFFFFFu, s1, o);
        s2 += __shfl_xor_sync(0xFFFFFFFFu, s2, o);
    }
    if (lane == 0) { g_as[w] = s1; g_ad[w] = s2; }
}

// ---------------- warp-per-dst segment softmax + aggregation -----------------
template <int F>
__global__ void k_agg(const float* __restrict__ h, const float* __restrict__ bias,
                      float* __restrict__ out) {
    int node = (blockIdx.x * blockDim.x + threadIdx.x) >> 5;
    int lane = threadIdx.x & 31;
    if (node >= NN) return;
    int beg = g_off[node], end = g_off[node + 1];
    float adn = g_ad[node];

    float m = -1e30f;
    for (int j = beg + lane; j < end; j += 32) {
        float e = g_as[g_esrc[j]] + adn;
        e = e > 0.f ? e : 0.2f * e;
        m = fmaxf(m, e);
    }
#pragma unroll
    for (int o = 16; o; o >>= 1) m = fmaxf(m, __shfl_xor_sync(0xFFFFFFFFu, m, o));

    float den = 0.f;
    for (int j = beg + lane; j < end; j += 32) {
        float e = g_as[g_esrc[j]] + adn;
        e = e > 0.f ? e : 0.2f * e;
        den += expf(e - m);
    }
#pragma unroll
    for (int o = 16; o; o >>= 1) den += __shfl_xor_sync(0xFFFFFFFFu, den, o);
    float inv = 1.f / den;

    float a0 = 0.f, a1 = 0.f;
    for (int j = beg; j < end; j++) {           // uniform across warp -> broadcast
        int s = g_esrc[j];
        float e = g_as[s] + adn;
        e = e > 0.f ? e : 0.2f * e;
        float wgt = expf(e - m) * inv;
        if (F == 64) {
            a0 += wgt * h[s * 64 + lane];
            a1 += wgt * h[s * 64 + 32 + lane];
        } else if (lane < F) {
            a0 += wgt * h[s * F + lane];
        }
    }
    if (F == 64) {
        out[node * 64 + lane]      = fmaxf(a0 + bias[lane], 0.f);
        out[node * 64 + 32 + lane] = fmaxf(a1 + bias[lane + 32], 0.f);
    } else if (lane < F) {
        out[node * F + lane] = fmaxf(a0 + bias[lane], 0.f);
    }
}

// ---------------- global mean pool + sigmoid ---------------------------------
__global__ void k_pool(const void* batch) {
    int i = blockIdx.x * blockDim.x + threadIdx.x;
    if (i >= NN) return;
    int b = ld_idx(batch, i);
    atomicAdd(&g_cnt[b], 1);
#pragma unroll
    for (int f = 0; f < CC; f++)
        atomicAdd(&g_pool[b * CC + f], g_h3[i * CC + f]);
}

__global__ void k_fin(float* __restrict__ out) {
    int i = blockIdx.x * blockDim.x + threadIdx.x;
    if (i >= GG * CC) return;
    int g = i / CC;
    float c = fmaxf((float)g_cnt[g], 1.f);
    float v = g_pool[i] / c;
    out[i] = 1.f / (1.f + expf(-v));
}

// -----------------------------------------------------------------------------
extern "C" void kernel_launch(void* const* d_in, const int* in_sizes, int n_in,
                              void* d_out, int out_size) {
    const float* x     = (const float*)d_in[0];
    const void*  ei    = d_in[1];
    // d_in[2] = edge_attr (unused by GATConv)
    const void*  batch = d_in[3];
    const float* W1  = (const float*)d_in[4];
    const float* a1s = (const float*)d_in[5];
    const float* a1d = (const float*)d_in[6];
    const float* b1  = (const float*)d_in[7];
    const float* W2  = (const float*)d_in[8];
    const float* a2s = (const float*)d_in[9];
    const float* a2d = (const float*)d_in[10];
    const float* b2  = (const float*)d_in[11];
    const float* W3  = (const float*)d_in[12];
    const float* a3s = (const float*)d_in[13];
    const float* a3d = (const float*)d_in[14];
    const float* b3  = (const float*)d_in[15];
    float* out = (float*)d_out;

    float *lin, *act, *h3;
    cudaGetSymbolAddress((void**)&lin, g_lin);
    cudaGetSymbolAddress((void**)&act, g_act);
    cudaGetSymbolAddress((void**)&h3,  g_h3);

    // CSR build (same graph reused by all 3 layers)
    k_detect<<<1, 32>>>(ei);
    k_zero<<<(NN + 255) / 256, 256>>>();
    k_hist<<<(ET + 255) / 256, 256>>>(ei);
    k_scan1<<<NBLK, 1024>>>();
    k_scan2<<<1, 32>>>();
    k_scan3<<<NBLK, 1024>>>();
    k_scatter<<<(ET + 255) / 256, 256>>>(ei);

    // Layer 1: 11 -> 64
    k_gemm<11, 64><<<(NN + 3) / 4, 64>>>(x, W1, lin);
    k_alpha<64><<<(NN + 7) / 8, 256>>>(lin, a1s, a1d);
    k_agg<64><<<(NN + 7) / 8, 256>>>(lin, b1, act);

    // Layer 2: 64 -> 64
    k_gemm<64, 64><<<(NN + 3) / 4, 64>>>(act, W2, lin);
    k_alpha<64><<<(NN + 7) / 8, 256>>>(lin, a2s, a2d);
    k_agg<64><<<(NN + 7) / 8, 256>>>(lin, b2, act);

    // Layer 3: 64 -> 8
    k_gemm<64, 8><<<(NN + 31) / 32, 64>>>(act, W3, lin);
    k_alpha<8><<<(NN + 7) / 8, 256>>>(lin, a3s, a3d);
    k_agg<8><<<(NN + 7) / 8, 256>>>(lin, b3, h3);

    // Pool + sigmoid
    k_pool<<<(NN + 255) / 256, 256>>>(batch);
    k_fin<<<2, 256>>>(out);
}

// round 2
// speedup vs baseline: 1.4319x; 1.4319x over previous
#include <cuda_runtime.h>
#include <math.h>

#define NN 50000
#define EE 800000
#define ET (EE + NN)
#define GG 64
#define HID 64
#define CC 8
#define NBLK 49   // ceil(NN/1024)

// ---------------- scratch (static device globals; no allocation) -------------
__device__ __align__(256) float g_lin[NN * HID];   // gemm output (h) per layer
__device__ __align__(256) float g_act[NN * HID];   // post-aggregation activations
__device__ float g_as[NN];
__device__ float g_ad[NN];
__device__ int   g_deg[NN];
__device__ int   g_pos[NN];
__device__ int   g_off[NN + 1];
__device__ int   g_esrc[ET];
__device__ int   g_part[NBLK];
__device__ float g_pool[GG * CC];
__device__ int   g_cnt[GG];
__device__ int   g_is64;

// ---------------- index dtype handling (int64 vs int32) ----------------------
__device__ __forceinline__ int ld_idx(const void* p, long long i) {
    return g_is64 ? (int)((const long long*)p)[i] : ((const int*)p)[i];
}

// ---------------- init: dtype detect + zero all counters ---------------------
__global__ void k_init(const void* ei) {
    int i = blockIdx.x * blockDim.x + threadIdx.x;
    if (i == 0) {
        const int* p = (const int*)ei;
        int ok = 1;
        // int64 little-endian: high words of node ids (< 2^31) are all zero.
        for (int q = 0; q < 64; q++) ok &= (p[2 * q + 1] == 0);
        g_is64 = ok;
    }
    if (i < NN) { g_deg[i] = 0; g_pos[i] = 0; }
    if (i < GG * CC) g_pool[i] = 0.f;
    if (i < GG) g_cnt[i] = 0;
}

// ---------------- CSR build --------------------------------------------------
__global__ void k_hist(const void* ei) {
    int e = blockIdx.x * blockDim.x + threadIdx.x;
    if (e >= ET) return;
    int d = (e < EE) ? ld_idx(ei, (long long)EE + e) : (e - EE);
    atomicAdd(&g_deg[d], 1);
}

__global__ void k_scan1() {
    __shared__ int s[1024];
    int tid = threadIdx.x;
    int i = blockIdx.x * 1024 + tid;
    int v = (i < NN) ? g_deg[i] : 0;
    s[tid] = v;
    __syncthreads();
    for (int off = 1; off < 1024; off <<= 1) {
        int t = (tid >= off) ? s[tid - off] : 0;
        __syncthreads();
        s[tid] += t;
        __syncthreads();
    }
    if (i < NN) g_off[i + 1] = s[tid];
    if (tid == 1023) g_part[blockIdx.x] = s[1023];
}

// scan2 merged into scan3: every block computes the partial prefix itself
__global__ void k_scan3() {
    __shared__ int spp[NBLK];
    int tid = threadIdx.x;
    if (tid < NBLK) spp[tid] = g_part[tid];
    __syncthreads();
    if (tid == 0) {
        int run = 0;
        for (int q = 0; q < NBLK; q++) { int v = spp[q]; spp[q] = run; run += v; }
    }
    __syncthreads();
    int add = spp[blockIdx.x];
    int i = blockIdx.x * 1024 + tid;
    if (i < NN) g_off[i + 1] += add;
    if (i == 0) g_off[0] = 0;
}

__global__ void k_scatter(const void* ei) {
    int e = blockIdx.x * blockDim.x + threadIdx.x;
    if (e >= ET) return;
    int s, d;
    if (e < EE) { s = ld_idx(ei, e); d = ld_idx(ei, (long long)EE + e); }
    else        { s = d = e - EE; }
    int p = g_off[d] + atomicAdd(&g_pos[d], 1);
    g_esrc[p] = s;
}

// ---------------- GEMM layer1: 11 -> 64, fused alpha -------------------------
__global__ void k_gemm1(const float* __restrict__ x, const float* __restrict__ W,
                        const float* __restrict__ a_s, const float* __restrict__ a_d,
                        float* __restrict__ h) {
    const int FI = 11, FO = 64, NPT = 4;
    __shared__ float xs[NPT * FI];
    __shared__ float red[2][NPT][2];
    int tid = threadIdx.x;   // 64 threads
    int nodeBase = blockIdx.x * NPT;
    for (int i = tid; i < NPT * FI; i += 64) {
        int n = nodeBase + i / FI;
        xs[i] = (n < NN) ? x[(long long)n * FI + (i % FI)] : 0.f;
    }
    __syncthreads();
    int f = tid;
    float acc[NPT] = {};
    for (int k = 0; k < FI; k++) {
        float w = W[k * FO + f];
#pragma unroll
        for (int i = 0; i < NPT; i++) acc[i] += xs[i * FI + k] * w;
    }
    float asf = a_s[f], adf = a_d[f];
    float ps[NPT], pd[NPT];
#pragma unroll
    for (int i = 0; i < NPT; i++) {
        int n = nodeBase + i;
        if (n < NN) h[(long long)n * FO + f] = acc[i];
        ps[i] = acc[i] * asf; pd[i] = acc[i] * adf;
    }
#pragma unroll
    for (int i = 0; i < NPT; i++)
#pragma unroll
        for (int o = 16; o; o >>= 1) {
            ps[i] += __shfl_xor_sync(0xFFFFFFFFu, ps[i], o);
            pd[i] += __shfl_xor_sync(0xFFFFFFFFu, pd[i], o);
        }
    int warp = tid >> 5, lane = tid & 31;
    if (lane == 0)
#pragma unroll
        for (int i = 0; i < NPT; i++) { red[warp][i][0] = ps[i]; red[warp][i][1] = pd[i]; }
    __syncthreads();
    if (tid == 0)
#pragma unroll
        for (int i = 0; i < NPT; i++) {
            int n = nodeBase + i;
            if (n < NN) {
                g_as[n] = red[0][i][0] + red[1][i][0];
                g_ad[n] = red[0][i][1] + red[1][i][1];
            }
        }
}

// ---------------- GEMM 64 -> 64, register tiled 4x4, fused alpha -------------
__global__ void k_gemm64(const float* __restrict__ x, const float* __restrict__ W,
                         const float* __restrict__ a_s, const float* __restrict__ a_d,
                         float* __restrict__ h) {
    __shared__ float ws[64 * 64];
    __shared__ float xsT[64 * 32];
    int tid = threadIdx.x;   // 128
    int nb = blockIdx.x * 32;
    // load W (coalesced float4)
    {
        const float4* W4 = (const float4*)W;
        float4* ws4 = (float4*)ws;
        for (int i = tid; i < 1024; i += 128) ws4[i] = W4[i];
    }
    // load x transposed into xsT[k][n]
    {
        int n = tid & 31, kc = tid >> 5;  // kc 0..3, 16 k each
        bool ok = (nb + n) < NN;
        const float4* xr = (const float4*)(x + (long long)(nb + n) * 64 + kc * 16);
#pragma unroll
        for (int q = 0; q < 4; q++) {
            float4 v = ok ? xr[q] : make_float4(0.f, 0.f, 0.f, 0.f);
            int k = kc * 16 + q * 4;
            xsT[(k + 0) * 32 + n] = v.x; xsT[(k + 1) * 32 + n] = v.y;
            xsT[(k + 2) * 32 + n] = v.z; xsT[(k + 3) * 32 + n] = v.w;
        }
    }
    __syncthreads();
    int tf = tid & 15, tn = tid >> 4;   // tf 0..15 (4 feats), tn 0..7 (4 nodes)
    float acc[4][4] = {};
    for (int k = 0; k < 64; k++) {
        float4 xv = *(const float4*)&xsT[k * 32 + tn * 4];
        float4 wv = *(const float4*)&ws[k * 64 + tf * 4];
        float xa[4] = {xv.x, xv.y, xv.z, xv.w};
        float wa[4] = {wv.x, wv.y, wv.z, wv.w};
#pragma unroll
        for (int i = 0; i < 4; i++)
#pragma unroll
            for (int j = 0; j < 4; j++) acc[i][j] += xa[i] * wa[j];
    }
    float4 as4 = ((const float4*)a_s)[tf];
    float4 ad4 = ((const float4*)a_d)[tf];
    float asA[4] = {as4.x, as4.y, as4.z, as4.w};
    float adA[4] = {ad4.x, ad4.y, ad4.z, ad4.w};
    float ps[4], pd[4];
#pragma unroll
    for (int i = 0; i < 4; i++) {
        int n = nb + tn * 4 + i;
        float s = 0.f, dd = 0.f;
#pragma unroll
        for (int j = 0; j < 4; j++) { s += acc[i][j] * asA[j]; dd += acc[i][j] * adA[j]; }
        ps[i] = s; pd[i] = dd;
        if (n < NN)
            *(float4*)&h[(long long)n * 64 + tf * 4] =
                make_float4(acc[i][0], acc[i][1], acc[i][2], acc[i][3]);
    }
#pragma unroll
    for (int i = 0; i < 4; i++)
#pragma unroll
        for (int o = 8; o; o >>= 1) {
            ps[i] += __shfl_xor_sync(0xFFFFFFFFu, ps[i], o);
            pd[i] += __shfl_xor_sync(0xFFFFFFFFu, pd[i], o);
        }
    if (tf == 0)
#pragma unroll
        for (int i = 0; i < 4; i++) {
            int n = nb + tn * 4 + i;
            if (n < NN) { g_as[n] = ps[i]; g_ad[n] = pd[i]; }
        }
}

// ---------------- GEMM layer3: 64 -> 8, fused alpha --------------------------
__global__ void k_gemm3(const float* __restrict__ x, const float* __restrict__ W,
                        const float* __restrict__ a_s, const float* __restrict__ a_d,
                        float* __restrict__ h) {
    const int FI = 64, FO = 8, NPT = 4, GROUPS = 8, NPB = 32;
    __shared__ float xs[NPB * FI];
    int tid = threadIdx.x;   // 64
    int nodeBase = blockIdx.x * NPB;
    for (int i = tid; i < NPB * FI; i += 64) {
        int n = nodeBase + i / FI;
        xs[i] = (n < NN) ? x[(long long)n * FI + (i % FI)] : 0.f;
    }
    __syncthreads();
    int gq = tid / FO, f = tid % FO;
    float acc[NPT] = {};
    for (int k = 0; k < FI; k++) {
        float w = W[k * FO + f];
#pragma unroll
        for (int i = 0; i < NPT; i++) acc[i] += xs[(gq * NPT + i) * FI + k] * w;
    }
    float asf = a_s[f], adf = a_d[f];
    float ps[NPT], pd[NPT];
#pragma unroll
    for (int i = 0; i < NPT; i++) {
        int n = nodeBase + gq * NPT + i;
        if (n < NN) h[(long long)n * FO + f] = acc[i];
        ps[i] = acc[i] * asf; pd[i] = acc[i] * adf;
    }
    // reduce within each 8-lane subgroup
#pragma unroll
    for (int i = 0; i < NPT; i++)
#pragma unroll
        for (int o = 4; o; o >>= 1) {
            ps[i] += __shfl_xor_sync(0xFFFFFFFFu, ps[i], o);
            pd[i] += __shfl_xor_sync(0xFFFFFFFFu, pd[i], o);
        }
    if (f == 0)
#pragma unroll
        for (int i = 0; i < NPT; i++) {
            int n = nodeBase + gq * NPT + i;
            if (n < NN) { g_as[n] = ps[i]; g_ad[n] = pd[i]; }
        }
}

// ---- warp-per-dst segment softmax + aggregation, single gather per edge -----
template <int F, bool POOL>
__global__ void k_agg(const float* __restrict__ h, const float* __restrict__ bias,
                      float* __restrict__ out, const void* batch) {
    int node = (blockIdx.x * blockDim.x + threadIdx.x) >> 5;
    int lane = threadIdx.x & 31;
    if (node >= NN) return;
    int beg = g_off[node], end = g_off[node + 1];
    float adn = g_ad[node];

    // cache up to 64 edges in registers (avg degree ~17; self-loop => >=1 edge)
    int s0 = 0, s1 = 0;
    float e0 = -1e30f, e1 = -1e30f;
    int j0 = beg + lane, j1 = beg + 32 + lane;
    if (j0 < end) { s0 = g_esrc[j0]; float t = g_as[s0] + adn; e0 = t > 0.f ? t : 0.2f * t; }
    if (j1 < end) { s1 = g_esrc[j1]; float t = g_as[s1] + adn; e1 = t > 0.f ? t : 0.2f * t; }
    float m = fmaxf(e0, e1);
    for (int j = beg + 64 + lane; j < end; j += 32) {   // rare tail
        int s = g_esrc[j]; float t = g_as[s] + adn; t = t > 0.f ? t : 0.2f * t;
        m = fmaxf(m, t);
    }
#pragma unroll
    for (int o = 16; o; o >>= 1) m = fmaxf(m, __shfl_xor_sync(0xFFFFFFFFu, m, o));

    float w0 = (j0 < end) ? __expf(e0 - m) : 0.f;
    float w1 = (j1 < end) ? __expf(e1 - m) : 0.f;
    float den = w0 + w1;
    for (int j = beg + 64 + lane; j < end; j += 32) {
        int s = g_esrc[j]; float t = g_as[s] + adn; t = t > 0.f ? t : 0.2f * t;
        den += __expf(t - m);
    }
#pragma unroll
    for (int o = 16; o; o >>= 1) den += __shfl_xor_sync(0xFFFFFFFFu, den, o);
    float inv = 1.f / den;
    w0 *= inv; w1 *= inv;

    float a0 = 0.f, a1 = 0.f;
    int d = end - beg;
    int dc = d < 64 ? d : 64;
    for (int jj = 0; jj < dc; jj++) {
        int sl = jj & 31;
        int s; float w;
        if (jj < 32) { s = __shfl_sync(0xFFFFFFFFu, s0, sl); w = __shfl_sync(0xFFFFFFFFu, w0, sl); }
        else         { s = __shfl_sync(0xFFFFFFFFu, s1, sl); w = __shfl_sync(0xFFFFFFFFu, w1, sl); }
        if (F == 64) { a0 += w * h[s * 64 + lane]; a1 += w * h[s * 64 + 32 + lane]; }
        else if (lane < F) a0 += w * h[s * F + lane];
    }
    for (int j = beg + 64; j < end; j++) {   // rare tail (uniform)
        int s = g_esrc[j];
        float t = g_as[s] + adn; t = t > 0.f ? t : 0.2f * t;
        float w = __expf(t - m) * inv;
        if (F == 64) { a0 += w * h[s * 64 + lane]; a1 += w * h[s * 64 + 32 + lane]; }
        else if (lane < F) a0 += w * h[s * F + lane];
    }

    if (!POOL) {
        if (F == 64) {
            out[node * 64 + lane]      = fmaxf(a0 + bias[lane], 0.f);
            out[node * 64 + 32 + lane] = fmaxf(a1 + bias[lane + 32], 0.f);
        } else if (lane < F) {
            out[node * F + lane] = fmaxf(a0 + bias[lane], 0.f);
        }
    } else {
        int b = ld_idx(batch, node);
        if (lane < F) atomicAdd(&g_pool[b * CC + lane], fmaxf(a0 + bias[lane], 0.f));
        if (lane == 0) atomicAdd(&g_cnt[b], 1);
    }
}

// ---------------- final mean + sigmoid ---------------------------------------
__global__ void k_fin(float* __restrict__ out) {
    int i = blockIdx.x * blockDim.x + threadIdx.x;
    if (i >= GG * CC) return;
    int g = i / CC;
    float c = fmaxf((float)g_cnt[g], 1.f);
    float v = g_pool[i] / c;
    out[i] = 1.f / (1.f + __expf(-v));
}

// -----------------------------------------------------------------------------
extern "C" void kernel_launch(void* const* d_in, const int* in_sizes, int n_in,
                              void* d_out, int out_size) {
    const float* x     = (const float*)d_in[0];
    const void*  ei    = d_in[1];
    const void*  batch = d_in[3];
    const float* W1  = (const float*)d_in[4];
    const float* a1s = (const float*)d_in[5];
    const float* a1d = (const float*)d_in[6];
    const float* b1  = (const float*)d_in[7];
    const float* W2  = (const float*)d_in[8];
    const float* a2s = (const float*)d_in[9];
    const float* a2d = (const float*)d_in[10];
    const float* b2  = (const float*)d_in[11];
    const float* W3  = (const float*)d_in[12];
    const float* a3s = (const float*)d_in[13];
    const float* a3d = (const float*)d_in[14];
    const float* b3  = (const float*)d_in[15];
    float* out = (float*)d_out;

    float *lin, *act;
    cudaGetSymbolAddress((void**)&lin, g_lin);
    cudaGetSymbolAddress((void**)&act, g_act);

    // CSR build (same graph reused by all 3 layers)
    k_init<<<(NN + 255) / 256, 256>>>(ei);
    k_hist<<<(ET + 255) / 256, 256>>>(ei);
    k_scan1<<<NBLK, 1024>>>();
    k_scan3<<<NBLK, 1024>>>();
    k_scatter<<<(ET + 255) / 256, 256>>>(ei);

    // Layer 1: 11 -> 64
    k_gemm1<<<(NN + 3) / 4, 64>>>(x, W1, a1s, a1d, lin);
    k_agg<64, false><<<(NN + 7) / 8, 256>>>(lin, b1, act, batch);

    // Layer 2: 64 -> 64
    k_gemm64<<<(NN + 31) / 32, 128>>>(act, W2, a2s, a2d, lin);
    k_agg<64, false><<<(NN + 7) / 8, 256>>>(lin, b2, act, batch);

    // Layer 3: 64 -> 8
    k_gemm3<<<(NN + 31) / 32, 64>>>(act, W3, a3s, a3d, lin);
    k_agg<8, true><<<(NN + 7) / 8, 256>>>(lin, b3, act, batch);

    // mean + sigmoid
    k_fin<<<2, 256>>>(out);
}